// round 9
// baseline (speedup 1.0000x reference)
#include <cuda_runtime.h>
#include <cuda_fp16.h>
#include <cstdint>

// CrossInferenceBlock via fp16 split-precision mma.sync (HMMA):
//  tp    = batch @ [a_w|b_w] + bias   (65536 x 512)  1-pass (w hi), out hi/lo
//  featsT[t][f][s] = (batch @ g_w + g_b)^T per t     1-pass, out hi only
//  fused per t:  attn = theta@phi^T (3-pass, fp16 in SMEM)
//                out  = attn @ feats / 512 (1-pass, fp32)
// GEMM: C[m][n] = sum_k A[m,k]*B[n,k], all K-major fp16.

#define TT 256
#define SS 256
#define FF 1024
#define AA 256

// ------------------------------- static scratch
__device__ __align__(16) __half g_batchH[67108864];  // [65536][1024]
__device__ __align__(16) __half g_wTH[524288];       // [512][1024] = aT|bT (hi)
__device__ __align__(16) __half g_gTH[1048576];      // g_w^T (hi)
__device__ __align__(16) __half g_tpH[33554432];     // [65536][512] theta|phi
__device__ __align__(16) __half g_tpL[33554432];
__device__ __align__(16) __half g_featsTH[67108864]; // [256][1024][256]

// ------------------------------- helpers
__device__ __forceinline__ uint32_t smem_u32(const void* p) {
    uint32_t a;
    asm("{ .reg .u64 t; cvta.to.shared.u64 t, %1; cvt.u32.u64 %0, t; }"
        : "=r"(a) : "l"(p));
    return a;
}
__device__ __forceinline__ void cpasync16(uint32_t s, const void* g) {
    asm volatile("cp.async.cg.shared.global [%0], [%1], 16;" :: "r"(s), "l"(g));
}
__device__ __forceinline__ void cp_commit() { asm volatile("cp.async.commit_group;"); }
template <int N>
__device__ __forceinline__ void cp_wait() {
    asm volatile("cp.async.wait_group %0;" :: "n"(N));
}
__device__ __forceinline__ uint4 ldsm4(uint32_t a) {
    uint4 r;
    asm volatile("ldmatrix.sync.aligned.m8n8.x4.shared.b16 {%0,%1,%2,%3}, [%4];"
                 : "=r"(r.x), "=r"(r.y), "=r"(r.z), "=r"(r.w) : "r"(a));
    return r;
}
__device__ __forceinline__ void mma_f16(float* c, const uint4& a,
                                        uint32_t b0, uint32_t b1) {
    asm volatile(
        "mma.sync.aligned.m16n8k16.row.col.f32.f16.f16.f32 "
        "{%0,%1,%2,%3},{%4,%5,%6,%7},{%8,%9},{%0,%1,%2,%3};"
        : "+f"(c[0]), "+f"(c[1]), "+f"(c[2]), "+f"(c[3])
        : "r"(a.x), "r"(a.y), "r"(a.z), "r"(a.w), "r"(b0), "r"(b1));
}
__device__ __forceinline__ void split2h(float v0, float v1, uint32_t& h, uint32_t& l) {
    __half2 hh = __floats2half2_rn(v0, v1);
    float r0 = v0 - __low2float(hh);
    float r1 = v1 - __high2float(hh);
    __half2 ll = __floats2half2_rn(r0, r1);
    h = *(uint32_t*)&hh;
    l = *(uint32_t*)&ll;
}

// ------------------------------- converters
__global__ void cvt_kernel(const float* __restrict__ in, __half* __restrict__ oh,
                           long n) {
    long i = ((long)blockIdx.x * blockDim.x + threadIdx.x) * 8;
    if (i >= n) return;
    float4 v0 = *(const float4*)(in + i);
    float4 v1 = *(const float4*)(in + i + 4);
    __half2 a = __floats2half2_rn(v0.x, v0.y);
    __half2 b = __floats2half2_rn(v0.z, v0.w);
    __half2 c = __floats2half2_rn(v1.x, v1.y);
    __half2 d = __floats2half2_rn(v1.z, v1.w);
    *(uint4*)(oh + i) = make_uint4(*(uint32_t*)&a, *(uint32_t*)&b,
                                   *(uint32_t*)&c, *(uint32_t*)&d);
}

__global__ void transpose_cvt_kernel(const float* __restrict__ in,
                                     __half* __restrict__ oh, int R, int C) {
    __shared__ float t[32][33];
    int c0 = blockIdx.x * 32, r0 = blockIdx.y * 32;
    int x = threadIdx.x, y = threadIdx.y;  // 32 x 8
#pragma unroll
    for (int i = 0; i < 32; i += 8)
        t[y + i][x] = in[(long)(r0 + y + i) * C + c0 + x];
    __syncthreads();
#pragma unroll
    for (int i = 0; i < 32; i += 8)
        oh[(long)(c0 + y + i) * R + r0 + x] = __float2half_rn(t[x][y + i]);
}

// ------------------------------- GEMM: BM=128 BN=128 BK=64, 3-stage cp.async
static constexpr int TILE = 16384;  // 128 x 64 fp16
static constexpr int OFF_AH = 0;
static constexpr int OFF_BH = TILE;
static constexpr int OFF_BL = 2 * TILE;  // NPASS >= 2
static constexpr int OFF_AL = 3 * TILE;  // NPASS == 3

// NPASS: 1 = Ahi*Bhi ; 2 = + Ahi*Blo ; 3 = + Alo*Bhi
// BMODE: 0 none, 1 col-bias (bias n<256 / bias2 n>=256), 2 row-bias (bias[m])
// OUTM : 0 = fp16 hi only, 1 = fp16 hi+lo, 2 = fp32
template <int NPASS, int BMODE, int OUTM>
__global__ void __launch_bounds__(256, NPASS == 1 ? 2 : 1) gemm_hmma(
    const __half* __restrict__ Ah, const __half* __restrict__ Al,
    const __half* __restrict__ Bh, const __half* __restrict__ Bl,
    const float* __restrict__ bias, const float* __restrict__ bias2,
    __half* __restrict__ Ch, __half* __restrict__ Cl, float* __restrict__ Cf,
    int N, int K, int lda, int ldb, int ldc, float scale,
    long sA, long sB, long sC)
{
    constexpr int STAGE = (NPASS + 1) * TILE;
    extern __shared__ __align__(1024) char smem[];
    const uint32_t sbase = smem_u32(smem);
    const int tid = threadIdx.x;
    const int wid = tid >> 5, lane = tid & 31;
    const long z = blockIdx.z;
    const int block_row = blockIdx.y * 128;
    const int block_col = blockIdx.x * 128;

    const __half* Az_h = Ah + z * sA + (long)block_row * lda;
    const __half* Az_l = (NPASS == 3) ? Al + z * sA + (long)block_row * lda : nullptr;
    const __half* Bz_h = Bh + z * sB + (long)block_col * ldb;
    const __half* Bz_l = (NPASS >= 2) ? Bl + z * sB + (long)block_col * ldb : nullptr;

    int c_row[4]; int c_co[4]; uint32_t c_so[4];
#pragma unroll
    for (int i = 0; i < 4; i++) {
        int q = tid + i * 256;
        int r = q >> 3, u = q & 7;
        c_row[i] = r;
        c_co[i] = u * 8;
        c_so[i] = (uint32_t)(r * 128 + ((u ^ (r & 7)) << 4));
    }

    auto load_stage = [&](int buf, int k0) {
        uint32_t sb = sbase + buf * STAGE;
#pragma unroll
        for (int i = 0; i < 4; i++) {
            long ga = (long)c_row[i] * lda + k0 + c_co[i];
            long gb = (long)c_row[i] * ldb + k0 + c_co[i];
            cpasync16(sb + OFF_AH + c_so[i], Az_h + ga);
            if (NPASS == 3) cpasync16(sb + OFF_AL + c_so[i], Az_l + ga);
            cpasync16(sb + OFF_BH + c_so[i], Bz_h + gb);
            if (NPASS >= 2) cpasync16(sb + OFF_BL + c_so[i], Bz_l + gb);
        }
    };

    const int wm = wid & 1, wn = wid >> 1;
    const int arow = wm * 64 + (lane & 15);
    const uint32_t asel = ((lane >> 4) & 1) * 16;
    const uint32_t axr = (uint32_t)((arow & 7) << 4);
    const int brow = wn * 32 + (lane & 7) + ((lane & 16) ? 8 : 0);
    const uint32_t bsel = (lane & 8) ? 16u : 0u;
    const uint32_t bxr = (uint32_t)((brow & 7) << 4);

    float acc[4][4][4];
#pragma unroll
    for (int a = 0; a < 4; a++)
#pragma unroll
        for (int b = 0; b < 4; b++)
#pragma unroll
            for (int c = 0; c < 4; c++) acc[a][b][c] = 0.0f;

    const int NT = K >> 6;
    load_stage(0, 0);
    cp_commit();
    if (NT > 1) load_stage(1, 64);
    cp_commit();

    int buf = 0;
    for (int it = 0; it < NT; it++) {
        cp_wait<1>();
        __syncthreads();
        if (it + 2 < NT) load_stage((it + 2) % 3, (it + 2) << 6);
        cp_commit();

        const uint32_t sb = sbase + buf * STAGE;
#pragma unroll
        for (int kk = 0; kk < 4; kk++) {
            uint4 ah[4], al4[4], bhf[2], blf[2];
#pragma unroll
            for (int mi = 0; mi < 4; mi++) {
                uint32_t ro = (uint32_t)((arow + mi * 16) * 128) +
                              (((uint32_t)(kk * 32) + asel) ^ axr);
                ah[mi] = ldsm4(sb + OFF_AH + ro);
                if (NPASS == 3) al4[mi] = ldsm4(sb + OFF_AL + ro);
            }
#pragma unroll
            for (int pi = 0; pi < 2; pi++) {
                uint32_t ro = (uint32_t)((brow + pi * 16) * 128) +
                              (((uint32_t)(kk * 32) + bsel) ^ bxr);
                bhf[pi] = ldsm4(sb + OFF_BH + ro);
                if (NPASS >= 2) blf[pi] = ldsm4(sb + OFF_BL + ro);
            }
#pragma unroll
            for (int mi = 0; mi < 4; mi++) {
#pragma unroll
                for (int ni = 0; ni < 4; ni++) {
                    const int pi = ni >> 1;
                    const bool up = ni & 1;
                    uint32_t bh0 = up ? bhf[pi].z : bhf[pi].x;
                    uint32_t bh1 = up ? bhf[pi].w : bhf[pi].y;
                    mma_f16(acc[mi][ni], ah[mi], bh0, bh1);
                    if (NPASS >= 2) {
                        uint32_t bl0 = up ? blf[pi].z : blf[pi].x;
                        uint32_t bl1 = up ? blf[pi].w : blf[pi].y;
                        mma_f16(acc[mi][ni], ah[mi], bl0, bl1);
                    }
                    if (NPASS == 3)
                        mma_f16(acc[mi][ni], al4[mi], bh0, bh1);
                }
            }
        }
        buf = (buf + 1) % 3;
    }

    const int grow0 = block_row + wm * 64 + (lane >> 2);
    const int gcol0 = block_col + wn * 32 + (lane & 3) * 2;
#pragma unroll
    for (int mi = 0; mi < 4; mi++) {
#pragma unroll
        for (int ni = 0; ni < 4; ni++) {
            float v0 = acc[mi][ni][0], v1 = acc[mi][ni][1];
            float v2 = acc[mi][ni][2], v3 = acc[mi][ni][3];
            const int r0 = grow0 + mi * 16, r1 = r0 + 8;
            const int cc = gcol0 + ni * 8;
            if (BMODE == 1) {
                float b0 = (cc < 256) ? bias[cc] : bias2[cc - 256];
                float b1 = (cc + 1 < 256) ? bias[cc + 1] : bias2[cc + 1 - 256];
                v0 += b0; v1 += b1; v2 += b0; v3 += b1;
            }
            if (BMODE == 2) {
                float ba = bias[r0], bb = bias[r1];
                v0 += ba; v1 += ba; v2 += bb; v3 += bb;
            }
            v0 *= scale; v1 *= scale; v2 *= scale; v3 *= scale;
            const long o0 = z * sC + (long)r0 * ldc + cc;
            const long o1 = z * sC + (long)r1 * ldc + cc;
            if (OUTM == 0) {
                __half2 p0 = __floats2half2_rn(v0, v1);
                __half2 p1 = __floats2half2_rn(v2, v3);
                *(uint32_t*)(Ch + o0) = *(uint32_t*)&p0;
                *(uint32_t*)(Ch + o1) = *(uint32_t*)&p1;
            } else if (OUTM == 1) {
                uint32_t h, l;
                split2h(v0, v1, h, l);
                *(uint32_t*)(Ch + o0) = h;
                *(uint32_t*)(Cl + o0) = l;
                split2h(v2, v3, h, l);
                *(uint32_t*)(Ch + o1) = h;
                *(uint32_t*)(Cl + o1) = l;
            } else {
                *(float2*)(Cf + o0) = make_float2(v0, v1);
                *(float2*)(Cf + o1) = make_float2(v2, v3);
            }
        }
    }
}

// ------------------------------- fused attn+out kernel
// grid (2, 256): x = m-half, y = t. 256 threads.
// SMEM: [0, 64KB) attn as 4 swizzled 128x64 A-tiles; [64KB, 192KB) pipeline stages.
static constexpr int FO_ATTN  = 0;
static constexpr int FO_STG   = 65536;        // phase1: 2 x 64KB; phase2: 3 x 16KB
static constexpr int FO_SMEM  = 65536 + 131072;  // 192 KB

__global__ void __launch_bounds__(256, 1) fused_attn_out(
    const __half* __restrict__ tpH, const __half* __restrict__ tpL,
    const __half* __restrict__ featsTH, float* __restrict__ out, float scale)
{
    extern __shared__ __align__(1024) char smem[];
    const uint32_t sbase = smem_u32(smem);
    const int tid = threadIdx.x;
    const int wid = tid >> 5, lane = tid & 31;
    const long t = blockIdx.y;
    const int mhalf = blockIdx.x;

    int c_row[4]; int c_co[4]; uint32_t c_so[4];
#pragma unroll
    for (int i = 0; i < 4; i++) {
        int q = tid + i * 256;
        int r = q >> 3, u = q & 7;
        c_row[i] = r;
        c_co[i] = u * 8;
        c_so[i] = (uint32_t)(r * 128 + ((u ^ (r & 7)) << 4));
    }

    const int wm = wid & 1, wn = wid >> 1;
    const int arow = wm * 64 + (lane & 15);
    const uint32_t asel = ((lane >> 4) & 1) * 16;
    const uint32_t axr = (uint32_t)((arow & 7) << 4);
    const int brow = wn * 32 + (lane & 7) + ((lane & 16) ? 8 : 0);
    const uint32_t bsel = (lane & 8) ? 16u : 0u;
    const uint32_t bxr = (uint32_t)((brow & 7) << 4);
    const int grow_l = wm * 64 + (lane >> 2);     // local row 0..127
    const int gcol_l = wn * 32 + (lane & 3) * 2;  // local col 0..127

    // ================= Phase 1: attn rows [mhalf*128,+128) x 256, 3-pass =================
    const __half* Ah = tpH + (t * 256 + mhalf * 128) * 512;        // theta hi
    const __half* Al = tpL + (t * 256 + mhalf * 128) * 512;        // theta lo
    for (int nhalf = 0; nhalf < 2; nhalf++) {
        const __half* Bh = tpH + (t * 256 + nhalf * 128) * 512 + 256;  // phi hi
        const __half* Bl = tpL + (t * 256 + nhalf * 128) * 512 + 256;  // phi lo

        auto load1 = [&](int buf, int k0) {
            uint32_t sb = sbase + FO_STG + buf * 65536;
#pragma unroll
            for (int i = 0; i < 4; i++) {
                long go = (long)c_row[i] * 512 + k0 + c_co[i];
                cpasync16(sb + OFF_AH + c_so[i], Ah + go);
                cpasync16(sb + OFF_AL + c_so[i], Al + go);
                cpasync16(sb + OFF_BH + c_so[i], Bh + go);
                cpasync16(sb + OFF_BL + c_so[i], Bl + go);
            }
        };

        float acc[4][4][4];
#pragma unroll
        for (int a = 0; a < 4; a++)
#pragma unroll
            for (int b = 0; b < 4; b++)
#pragma unroll
                for (int c = 0; c < 4; c++) acc[a][b][c] = 0.0f;

        __syncthreads();   // prev readers done before overwriting stage bufs
        load1(0, 0);
        cp_commit();
        load1(1, 64);
        cp_commit();

        for (int it = 0; it < 4; it++) {
            cp_wait<1>();
            __syncthreads();
            const uint32_t sb = sbase + FO_STG + (it & 1) * 65536;
#pragma unroll
            for (int kk = 0; kk < 4; kk++) {
                uint4 ah[4], al4[4], bhf[2], blf[2];
#pragma unroll
                for (int mi = 0; mi < 4; mi++) {
                    uint32_t ro = (uint32_t)((arow + mi * 16) * 128) +
                                  (((uint32_t)(kk * 32) + asel) ^ axr);
                    ah[mi] = ldsm4(sb + OFF_AH + ro);
                    al4[mi] = ldsm4(sb + OFF_AL + ro);
                }
#pragma unroll
                for (int pi = 0; pi < 2; pi++) {
                    uint32_t ro = (uint32_t)((brow + pi * 16) * 128) +
                                  (((uint32_t)(kk * 32) + bsel) ^ bxr);
                    bhf[pi] = ldsm4(sb + OFF_BH + ro);
                    blf[pi] = ldsm4(sb + OFF_BL + ro);
                }
#pragma unroll
                for (int mi = 0; mi < 4; mi++) {
#pragma unroll
                    for (int ni = 0; ni < 4; ni++) {
                        const int pi = ni >> 1;
                        const bool up = ni & 1;
                        uint32_t bh0 = up ? bhf[pi].z : bhf[pi].x;
                        uint32_t bh1 = up ? bhf[pi].w : bhf[pi].y;
                        uint32_t bl0 = up ? blf[pi].z : blf[pi].x;
                        uint32_t bl1 = up ? blf[pi].w : blf[pi].y;
                        mma_f16(acc[mi][ni], ah[mi], bh0, bh1);
                        mma_f16(acc[mi][ni], ah[mi], bl0, bl1);
                        mma_f16(acc[mi][ni], al4[mi], bh0, bh1);
                    }
                }
            }
            __syncthreads();   // all warps done reading this buf
            if (it + 2 < 4) load1(it & 1, (it + 2) << 6);
            cp_commit();
        }

        // store attn fp16 into SMEM chunk tiles (K-major A-tile layout, swizzled)
#pragma unroll
        for (int mi = 0; mi < 4; mi++) {
#pragma unroll
            for (int ni = 0; ni < 4; ni++) {
                const int r0 = grow_l + mi * 16, r1 = r0 + 8;
                const int cglob = nhalf * 128 + gcol_l + ni * 8;
                const int chunk = cglob >> 6;
                const int ci = cglob & 63;
                __half2 p0 = __floats2half2_rn(acc[mi][ni][0], acc[mi][ni][1]);
                __half2 p1 = __floats2half2_rn(acc[mi][ni][2], acc[mi][ni][3]);
                uint32_t o0 = (uint32_t)(chunk * 16384 + r0 * 128 +
                               ((((ci >> 3) ^ (r0 & 7)) << 4) + (ci & 7) * 2));
                uint32_t o1 = (uint32_t)(chunk * 16384 + r1 * 128 +
                               ((((ci >> 3) ^ (r1 & 7)) << 4) + (ci & 7) * 2));
                *(uint32_t*)(smem + FO_ATTN + o0) = *(uint32_t*)&p0;
                *(uint32_t*)(smem + FO_ATTN + o1) = *(uint32_t*)&p1;
            }
        }
    }
    __syncthreads();   // attn SMEM complete

    // ================= Phase 2: out = attn @ feats, 32 B-tiles (8 nb x 4 kt) ========
    const __half* Bf = featsTH + t * 262144;   // [f][s], ldb = 256
    auto load2 = [&](int buf, int g) {         // g = nb*4 + kt
        uint32_t sb = sbase + FO_STG + buf * TILE;
        int nb = g >> 2, kt = g & 3;
#pragma unroll
        for (int i = 0; i < 4; i++) {
            long go = (long)(nb * 128 + c_row[i]) * 256 + kt * 64 + c_co[i];
            cpasync16(sb + c_so[i], Bf + go);
        }
    };

    load2(0, 0);
    cp_commit();
    load2(1, 1);
    cp_commit();

    float acc[4][4][4];
    float* outr = out + t * 262144 + (long)mhalf * 128 * 1024;

    int buf = 0;
    for (int g = 0; g < 32; g++) {
        if ((g & 3) == 0) {
#pragma unroll
            for (int a = 0; a < 4; a++)
#pragma unroll
                for (int b = 0; b < 4; b++)
#pragma unroll
                    for (int c = 0; c < 4; c++) acc[a][b][c] = 0.0f;
        }
        cp_wait<1>();
        __syncthreads();
        if (g + 2 < 32) load2((g + 2) % 3, g + 2);
        cp_commit();

        const uint32_t sbB = sbase + FO_STG + buf * TILE;
        const uint32_t sbA = sbase + FO_ATTN + (g & 3) * TILE;
#pragma unroll
        for (int kk = 0; kk < 4; kk++) {
            uint4 ah[4], bhf[2];
#pragma unroll
            for (int mi = 0; mi < 4; mi++) {
                uint32_t ro = (uint32_t)((arow + mi * 16) * 128) +
                              (((uint32_t)(kk * 32) + asel) ^ axr);
                ah[mi] = ldsm4(sbA + ro);
            }
#pragma unroll
            for (int pi = 0; pi < 2; pi++) {
                uint32_t ro = (uint32_t)((brow + pi * 16) * 128) +
                              (((uint32_t)(kk * 32) + bsel) ^ bxr);
                bhf[pi] = ldsm4(sbB + ro);
            }
#pragma unroll
            for (int mi = 0; mi < 4; mi++) {
#pragma unroll
                for (int ni = 0; ni < 4; ni++) {
                    const int pi = ni >> 1;
                    const bool up = ni & 1;
                    uint32_t b0 = up ? bhf[pi].z : bhf[pi].x;
                    uint32_t b1 = up ? bhf[pi].w : bhf[pi].y;
                    mma_f16(acc[mi][ni], ah[mi], b0, b1);
                }
            }
        }
        buf = (buf + 1) % 3;

        if ((g & 3) == 3) {
            const int nb = g >> 2;
#pragma unroll
            for (int mi = 0; mi < 4; mi++) {
#pragma unroll
                for (int ni = 0; ni < 4; ni++) {
                    const int r0 = grow_l + mi * 16, r1 = r0 + 8;
                    const int cc = nb * 128 + gcol_l + ni * 8;
                    *(float2*)(outr + (long)r0 * 1024 + cc) =
                        make_float2(acc[mi][ni][0] * scale, acc[mi][ni][1] * scale);
                    *(float2*)(outr + (long)r1 * 1024 + cc) =
                        make_float2(acc[mi][ni][2] * scale, acc[mi][ni][3] * scale);
                }
            }
        }
    }
}

static constexpr int SMEMB1 = 3 * 2 * TILE;  //  96 KB

// ------------------------------- launcher
extern "C" void kernel_launch(void* const* d_in, const int* in_sizes, int n_in,
                              void* d_out, int out_size)
{
    const float* batch = (const float*)d_in[0];
    const float* a_w   = (const float*)d_in[1];
    const float* a_b   = (const float*)d_in[2];
    const float* b_w   = (const float*)d_in[3];
    const float* b_b   = (const float*)d_in[4];
    const float* g_w   = (const float*)d_in[5];
    const float* g_b   = (const float*)d_in[6];
    float* out = (float*)d_out;

    void* p;
#define SYMH(v, s) cudaGetSymbolAddress(&p, s); __half* v = (__half*)p
    SYMH(batchH, g_batchH);
    SYMH(wTH, g_wTH);
    SYMH(gTH, g_gTH);
    SYMH(tpH, g_tpH);         SYMH(tpL, g_tpL);
    SYMH(featsTH, g_featsTH);
#undef SYMH

    static bool attr_done = false;
    if (!attr_done) {
        cudaFuncSetAttribute(gemm_hmma<1, 1, 1>,
                             cudaFuncAttributeMaxDynamicSharedMemorySize, SMEMB1);
        cudaFuncSetAttribute(gemm_hmma<1, 2, 0>,
                             cudaFuncAttributeMaxDynamicSharedMemorySize, SMEMB1);
        cudaFuncSetAttribute(fused_attn_out,
                             cudaFuncAttributeMaxDynamicSharedMemorySize, FO_SMEM);
        attr_done = true;
    }

    // converts
    cvt_kernel<<<32768, 256>>>(batch, batchH, (long)67108864);
    const dim3 tb(32, 8);
    transpose_cvt_kernel<<<dim3(AA / 32, FF / 32), tb>>>(a_w, wTH, FF, AA);
    transpose_cvt_kernel<<<dim3(AA / 32, FF / 32), tb>>>(
        b_w, wTH + 256 * 1024, FF, AA);
    transpose_cvt_kernel<<<dim3(FF / 32, FF / 32), tb>>>(g_w, gTH, FF, FF);

    // tp = batch @ [a_w|b_w] + bias : M=65536, N=512, K=1024 (1-pass, out hi/lo)
    gemm_hmma<1, 1, 1><<<dim3(4, 512, 1), 256, SMEMB1>>>(
        batchH, nullptr, wTH, nullptr, a_b, b_b, tpH, tpL, nullptr,
        512, 1024, 1024, 1024, 512, 1.0f, 0, 0, 0);

    // featsT[t][f][s]: per t, M=1024(f), N=256(s), K=1024 (1-pass, hi only)
    gemm_hmma<1, 2, 0><<<dim3(2, 8, 256), 256, SMEMB1>>>(
        gTH, nullptr, batchH, nullptr, g_b, nullptr, featsTH, nullptr, nullptr,
        256, 1024, 1024, 1024, 256, 1.0f, 0, (long)256 * 1024, (long)1024 * 256);

    // fused: attn (3-pass) + out (1-pass) per t
    fused_attn_out<<<dim3(2, 256), 256, FO_SMEM>>>(
        tpH, tpL, featsTH, out, 1.0f / (float)(SS + TT));
}

// round 10
// speedup vs baseline: 1.0184x; 1.0184x over previous
#include <cuda_runtime.h>
#include <cuda_fp16.h>
#include <cstdint>

// CrossInferenceBlock via fp16 split-precision mma.sync (HMMA):
//  tp    = batch @ [a_w|b_w] + bias   (65536 x 512)  1-pass (w hi), out hi/lo
//  featsT[t][f][s] = (batch @ g_w + g_b)^T per t     1-pass, out hi only
//  attn[t] = theta[t] @ phi[t]^T      (256 x 256)    3-pass, out hi only
//  out[t]  = (attn[t] @ feats[t])/512                1-pass, fp32, A-reuse kernel
// GEMM: C[m][n] = sum_k A[m,k]*B[n,k], all K-major fp16.

#define TT 256
#define SS 256
#define FF 1024
#define AA 256

// ------------------------------- static scratch
__device__ __align__(16) __half g_batchH[67108864];  // [65536][1024]
__device__ __align__(16) __half g_wTH[524288];       // [512][1024] = aT|bT (hi)
__device__ __align__(16) __half g_gTH[1048576];      // g_w^T (hi)
__device__ __align__(16) __half g_tpH[33554432];     // [65536][512] theta|phi
__device__ __align__(16) __half g_tpL[33554432];
__device__ __align__(16) __half g_attnH[16777216];   // [65536][256]
__device__ __align__(16) __half g_featsTH[67108864]; // [256][1024][256]

// ------------------------------- helpers
__device__ __forceinline__ uint32_t smem_u32(const void* p) {
    uint32_t a;
    asm("{ .reg .u64 t; cvta.to.shared.u64 t, %1; cvt.u32.u64 %0, t; }"
        : "=r"(a) : "l"(p));
    return a;
}
__device__ __forceinline__ void cpasync16(uint32_t s, const void* g) {
    asm volatile("cp.async.cg.shared.global [%0], [%1], 16;" :: "r"(s), "l"(g));
}
__device__ __forceinline__ void cp_commit() { asm volatile("cp.async.commit_group;"); }
template <int N>
__device__ __forceinline__ void cp_wait() {
    asm volatile("cp.async.wait_group %0;" :: "n"(N));
}
__device__ __forceinline__ uint4 ldsm4(uint32_t a) {
    uint4 r;
    asm volatile("ldmatrix.sync.aligned.m8n8.x4.shared.b16 {%0,%1,%2,%3}, [%4];"
                 : "=r"(r.x), "=r"(r.y), "=r"(r.z), "=r"(r.w) : "r"(a));
    return r;
}
__device__ __forceinline__ void mma_f16(float* c, const uint4& a,
                                        uint32_t b0, uint32_t b1) {
    asm volatile(
        "mma.sync.aligned.m16n8k16.row.col.f32.f16.f16.f32 "
        "{%0,%1,%2,%3},{%4,%5,%6,%7},{%8,%9},{%0,%1,%2,%3};"
        : "+f"(c[0]), "+f"(c[1]), "+f"(c[2]), "+f"(c[3])
        : "r"(a.x), "r"(a.y), "r"(a.z), "r"(a.w), "r"(b0), "r"(b1));
}
__device__ __forceinline__ void split2h(float v0, float v1, uint32_t& h, uint32_t& l) {
    __half2 hh = __floats2half2_rn(v0, v1);
    float r0 = v0 - __low2float(hh);
    float r1 = v1 - __high2float(hh);
    __half2 ll = __floats2half2_rn(r0, r1);
    h = *(uint32_t*)&hh;
    l = *(uint32_t*)&ll;
}

// ------------------------------- converters
__global__ void cvt_kernel(const float* __restrict__ in, __half* __restrict__ oh,
                           long n) {
    long i = ((long)blockIdx.x * blockDim.x + threadIdx.x) * 8;
    if (i >= n) return;
    float4 v0 = *(const float4*)(in + i);
    float4 v1 = *(const float4*)(in + i + 4);
    __half2 a = __floats2half2_rn(v0.x, v0.y);
    __half2 b = __floats2half2_rn(v0.z, v0.w);
    __half2 c = __floats2half2_rn(v1.x, v1.y);
    __half2 d = __floats2half2_rn(v1.z, v1.w);
    *(uint4*)(oh + i) = make_uint4(*(uint32_t*)&a, *(uint32_t*)&b,
                                   *(uint32_t*)&c, *(uint32_t*)&d);
}

__global__ void transpose_cvt_kernel(const float* __restrict__ in,
                                     __half* __restrict__ oh, int R, int C) {
    __shared__ float t[32][33];
    int c0 = blockIdx.x * 32, r0 = blockIdx.y * 32;
    int x = threadIdx.x, y = threadIdx.y;  // 32 x 8
#pragma unroll
    for (int i = 0; i < 32; i += 8)
        t[y + i][x] = in[(long)(r0 + y + i) * C + c0 + x];
    __syncthreads();
#pragma unroll
    for (int i = 0; i < 32; i += 8)
        oh[(long)(c0 + y + i) * R + r0 + x] = __float2half_rn(t[x][y + i]);
}

// ------------------------------- GEMM: BM=128 BN=128 BK=64, 3-stage cp.async
static constexpr int TILE = 16384;  // 128 x 64 fp16
static constexpr int OFF_AH = 0;
static constexpr int OFF_BH = TILE;
static constexpr int OFF_BL = 2 * TILE;  // NPASS >= 2
static constexpr int OFF_AL = 3 * TILE;  // NPASS == 3

// NPASS: 1 = Ahi*Bhi ; 2 = + Ahi*Blo ; 3 = + Alo*Bhi
// BMODE: 0 none, 1 col-bias (bias n<256 / bias2 n>=256), 2 row-bias (bias[m])
// OUTM : 0 = fp16 hi only, 1 = fp16 hi+lo, 2 = fp32
template <int NPASS, int BMODE, int OUTM>
__global__ void __launch_bounds__(256, NPASS == 1 ? 2 : 1) gemm_hmma(
    const __half* __restrict__ Ah, const __half* __restrict__ Al,
    const __half* __restrict__ Bh, const __half* __restrict__ Bl,
    const float* __restrict__ bias, const float* __restrict__ bias2,
    __half* __restrict__ Ch, __half* __restrict__ Cl, float* __restrict__ Cf,
    int N, int K, int lda, int ldb, int ldc, float scale,
    long sA, long sB, long sC)
{
    constexpr int STAGE = (NPASS + 1) * TILE;
    extern __shared__ __align__(1024) char smem[];
    const uint32_t sbase = smem_u32(smem);
    const int tid = threadIdx.x;
    const int wid = tid >> 5, lane = tid & 31;
    const long z = blockIdx.z;
    const int block_row = blockIdx.y * 128;
    const int block_col = blockIdx.x * 128;

    const __half* Az_h = Ah + z * sA + (long)block_row * lda;
    const __half* Az_l = (NPASS == 3) ? Al + z * sA + (long)block_row * lda : nullptr;
    const __half* Bz_h = Bh + z * sB + (long)block_col * ldb;
    const __half* Bz_l = (NPASS >= 2) ? Bl + z * sB + (long)block_col * ldb : nullptr;

    int c_row[4]; int c_co[4]; uint32_t c_so[4];
#pragma unroll
    for (int i = 0; i < 4; i++) {
        int q = tid + i * 256;
        int r = q >> 3, u = q & 7;
        c_row[i] = r;
        c_co[i] = u * 8;
        c_so[i] = (uint32_t)(r * 128 + ((u ^ (r & 7)) << 4));
    }

    auto load_stage = [&](int buf, int k0) {
        uint32_t sb = sbase + buf * STAGE;
#pragma unroll
        for (int i = 0; i < 4; i++) {
            long ga = (long)c_row[i] * lda + k0 + c_co[i];
            long gb = (long)c_row[i] * ldb + k0 + c_co[i];
            cpasync16(sb + OFF_AH + c_so[i], Az_h + ga);
            if (NPASS == 3) cpasync16(sb + OFF_AL + c_so[i], Az_l + ga);
            cpasync16(sb + OFF_BH + c_so[i], Bz_h + gb);
            if (NPASS >= 2) cpasync16(sb + OFF_BL + c_so[i], Bz_l + gb);
        }
    };

    const int wm = wid & 1, wn = wid >> 1;
    const int arow = wm * 64 + (lane & 15);
    const uint32_t asel = ((lane >> 4) & 1) * 16;
    const uint32_t axr = (uint32_t)((arow & 7) << 4);
    const int brow = wn * 32 + (lane & 7) + ((lane & 16) ? 8 : 0);
    const uint32_t bsel = (lane & 8) ? 16u : 0u;
    const uint32_t bxr = (uint32_t)((brow & 7) << 4);

    float acc[4][4][4];
#pragma unroll
    for (int a = 0; a < 4; a++)
#pragma unroll
        for (int b = 0; b < 4; b++)
#pragma unroll
            for (int c = 0; c < 4; c++) acc[a][b][c] = 0.0f;

    const int NT = K >> 6;
    load_stage(0, 0);
    cp_commit();
    if (NT > 1) load_stage(1, 64);
    cp_commit();

    int buf = 0;
    for (int it = 0; it < NT; it++) {
        cp_wait<1>();
        __syncthreads();
        if (it + 2 < NT) load_stage((it + 2) % 3, (it + 2) << 6);
        cp_commit();

        const uint32_t sb = sbase + buf * STAGE;
#pragma unroll
        for (int kk = 0; kk < 4; kk++) {
            uint4 ah[4], al4[4], bhf[2], blf[2];
#pragma unroll
            for (int mi = 0; mi < 4; mi++) {
                uint32_t ro = (uint32_t)((arow + mi * 16) * 128) +
                              (((uint32_t)(kk * 32) + asel) ^ axr);
                ah[mi] = ldsm4(sb + OFF_AH + ro);
                if (NPASS == 3) al4[mi] = ldsm4(sb + OFF_AL + ro);
            }
#pragma unroll
            for (int pi = 0; pi < 2; pi++) {
                uint32_t ro = (uint32_t)((brow + pi * 16) * 128) +
                              (((uint32_t)(kk * 32) + bsel) ^ bxr);
                bhf[pi] = ldsm4(sb + OFF_BH + ro);
                if (NPASS >= 2) blf[pi] = ldsm4(sb + OFF_BL + ro);
            }
#pragma unroll
            for (int mi = 0; mi < 4; mi++) {
#pragma unroll
                for (int ni = 0; ni < 4; ni++) {
                    const int pi = ni >> 1;
                    const bool up = ni & 1;
                    uint32_t bh0 = up ? bhf[pi].z : bhf[pi].x;
                    uint32_t bh1 = up ? bhf[pi].w : bhf[pi].y;
                    mma_f16(acc[mi][ni], ah[mi], bh0, bh1);
                    if (NPASS >= 2) {
                        uint32_t bl0 = up ? blf[pi].z : blf[pi].x;
                        uint32_t bl1 = up ? blf[pi].w : blf[pi].y;
                        mma_f16(acc[mi][ni], ah[mi], bl0, bl1);
                    }
                    if (NPASS == 3)
                        mma_f16(acc[mi][ni], al4[mi], bh0, bh1);
                }
            }
        }
        buf = (buf + 1) % 3;
    }

    const int grow0 = block_row + wm * 64 + (lane >> 2);
    const int gcol0 = block_col + wn * 32 + (lane & 3) * 2;
#pragma unroll
    for (int mi = 0; mi < 4; mi++) {
#pragma unroll
        for (int ni = 0; ni < 4; ni++) {
            float v0 = acc[mi][ni][0], v1 = acc[mi][ni][1];
            float v2 = acc[mi][ni][2], v3 = acc[mi][ni][3];
            const int r0 = grow0 + mi * 16, r1 = r0 + 8;
            const int cc = gcol0 + ni * 8;
            if (BMODE == 1) {
                float b0 = (cc < 256) ? bias[cc] : bias2[cc - 256];
                float b1 = (cc + 1 < 256) ? bias[cc + 1] : bias2[cc + 1 - 256];
                v0 += b0; v1 += b1; v2 += b0; v3 += b1;
            }
            if (BMODE == 2) {
                float ba = bias[r0], bb = bias[r1];
                v0 += ba; v1 += ba; v2 += bb; v3 += bb;
            }
            v0 *= scale; v1 *= scale; v2 *= scale; v3 *= scale;
            const long o0 = z * sC + (long)r0 * ldc + cc;
            const long o1 = z * sC + (long)r1 * ldc + cc;
            if (OUTM == 0) {
                __half2 p0 = __floats2half2_rn(v0, v1);
                __half2 p1 = __floats2half2_rn(v2, v3);
                *(uint32_t*)(Ch + o0) = *(uint32_t*)&p0;
                *(uint32_t*)(Ch + o1) = *(uint32_t*)&p1;
            } else if (OUTM == 1) {
                uint32_t h, l;
                split2h(v0, v1, h, l);
                *(uint32_t*)(Ch + o0) = h;
                *(uint32_t*)(Cl + o0) = l;
                split2h(v2, v3, h, l);
                *(uint32_t*)(Ch + o1) = h;
                *(uint32_t*)(Cl + o1) = l;
            } else {
                *(float2*)(Cf + o0) = make_float2(v0, v1);
                *(float2*)(Cf + o1) = make_float2(v2, v3);
            }
        }
    }
}

// ------------------------------- out kernel with A reuse
// grid (2, 256): x = m-half, y = t. 256 threads, 2 CTAs/SM.
// SMEM: [0, 64KB) attn A as 4 swizzled 128x64 K-tiles; [64KB, 112KB) 3-stage B ring.
static constexpr int AR_B    = 65536;
static constexpr int AR_SMEM = 65536 + 3 * TILE;   // 112 KB

__global__ void __launch_bounds__(256, 2) out_gemm_areuse(
    const __half* __restrict__ attnH, const __half* __restrict__ featsTH,
    float* __restrict__ out, float scale)
{
    extern __shared__ __align__(1024) char smem[];
    const uint32_t sbase = smem_u32(smem);
    const int tid = threadIdx.x;
    const int wid = tid >> 5, lane = tid & 31;
    const long t = blockIdx.y;
    const int mhalf = blockIdx.x;

    int c_row[4]; int c_co[4]; uint32_t c_so[4];
#pragma unroll
    for (int i = 0; i < 4; i++) {
        int q = tid + i * 256;
        int r = q >> 3, u = q & 7;
        c_row[i] = r;
        c_co[i] = u * 8;
        c_so[i] = (uint32_t)(r * 128 + ((u ^ (r & 7)) << 4));
    }

    // Load A slab: attn rows [mhalf*128, +128) x 256 cols, as 4 K-tiles (group 0)
    const __half* Aa = attnH + (t * 256 + mhalf * 128) * 256;
#pragma unroll
    for (int kt = 0; kt < 4; kt++) {
#pragma unroll
        for (int i = 0; i < 4; i++) {
            long ga = (long)c_row[i] * 256 + kt * 64 + c_co[i];
            cpasync16(sbase + (uint32_t)(kt * TILE) + c_so[i], Aa + ga);
        }
    }
    cp_commit();

    // B prologue (groups 1, 2)
    const __half* Bf = featsTH + t * 262144;   // [f][s], ldb = 256
    auto loadB = [&](int buf, int g) {         // g = nb*4 + kt
        uint32_t sb = sbase + AR_B + buf * TILE;
        int nb = g >> 2, kt = g & 3;
#pragma unroll
        for (int i = 0; i < 4; i++) {
            long go = (long)(nb * 128 + c_row[i]) * 256 + kt * 64 + c_co[i];
            cpasync16(sb + c_so[i], Bf + go);
        }
    };
    loadB(0, 0);
    cp_commit();
    loadB(1, 1);
    cp_commit();

    const int wm = wid & 1, wn = wid >> 1;
    const int arow = wm * 64 + (lane & 15);
    const uint32_t asel = ((lane >> 4) & 1) * 16;
    const uint32_t axr = (uint32_t)((arow & 7) << 4);
    const int brow = wn * 32 + (lane & 7) + ((lane & 16) ? 8 : 0);
    const uint32_t bsel = (lane & 8) ? 16u : 0u;
    const uint32_t bxr = (uint32_t)((brow & 7) << 4);
    const int grow_l = wm * 64 + (lane >> 2);
    const int gcol_l = wn * 32 + (lane & 3) * 2;

    float acc[4][4][4];
    float* outr = out + t * 262144 + (long)mhalf * 128 * 1024;

    int buf = 0;
    for (int g = 0; g < 32; g++) {
        if ((g & 3) == 0) {
#pragma unroll
            for (int a = 0; a < 4; a++)
#pragma unroll
                for (int b = 0; b < 4; b++)
#pragma unroll
                    for (int c = 0; c < 4; c++) acc[a][b][c] = 0.0f;
        }
        cp_wait<1>();          // first pass also drains the A-slab group
        __syncthreads();
        if (g + 2 < 32) loadB((g + 2) % 3, g + 2);
        cp_commit();

        const uint32_t sbB = sbase + AR_B + buf * TILE;
        const uint32_t sbA = sbase + (uint32_t)((g & 3) * TILE);
#pragma unroll
        for (int kk = 0; kk < 4; kk++) {
            uint4 ah[4], bhf[2];
#pragma unroll
            for (int mi = 0; mi < 4; mi++) {
                uint32_t ro = (uint32_t)((arow + mi * 16) * 128) +
                              (((uint32_t)(kk * 32) + asel) ^ axr);
                ah[mi] = ldsm4(sbA + ro);
            }
#pragma unroll
            for (int pi = 0; pi < 2; pi++) {
                uint32_t ro = (uint32_t)((brow + pi * 16) * 128) +
                              (((uint32_t)(kk * 32) + bsel) ^ bxr);
                bhf[pi] = ldsm4(sbB + ro);
            }
#pragma unroll
            for (int mi = 0; mi < 4; mi++) {
#pragma unroll
                for (int ni = 0; ni < 4; ni++) {
                    const int pi = ni >> 1;
                    const bool up = ni & 1;
                    uint32_t b0 = up ? bhf[pi].z : bhf[pi].x;
                    uint32_t b1 = up ? bhf[pi].w : bhf[pi].y;
                    mma_f16(acc[mi][ni], ah[mi], b0, b1);
                }
            }
        }
        buf = (buf + 1) % 3;

        if ((g & 3) == 3) {
            const int nb = g >> 2;
#pragma unroll
            for (int mi = 0; mi < 4; mi++) {
#pragma unroll
                for (int ni = 0; ni < 4; ni++) {
                    const int r0 = grow_l + mi * 16, r1 = r0 + 8;
                    const int cc = nb * 128 + gcol_l + ni * 8;
                    *(float2*)(outr + (long)r0 * 1024 + cc) =
                        make_float2(acc[mi][ni][0] * scale, acc[mi][ni][1] * scale);
                    *(float2*)(outr + (long)r1 * 1024 + cc) =
                        make_float2(acc[mi][ni][2] * scale, acc[mi][ni][3] * scale);
                }
            }
        }
    }
}

static constexpr int SMEMB1 = 3 * 2 * TILE;  //  96 KB
static constexpr int SMEMB3 = 3 * 4 * TILE;  // 192 KB

// ------------------------------- launcher
extern "C" void kernel_launch(void* const* d_in, const int* in_sizes, int n_in,
                              void* d_out, int out_size)
{
    const float* batch = (const float*)d_in[0];
    const float* a_w   = (const float*)d_in[1];
    const float* a_b   = (const float*)d_in[2];
    const float* b_w   = (const float*)d_in[3];
    const float* b_b   = (const float*)d_in[4];
    const float* g_w   = (const float*)d_in[5];
    const float* g_b   = (const float*)d_in[6];
    float* out = (float*)d_out;

    void* p;
#define SYMH(v, s) cudaGetSymbolAddress(&p, s); __half* v = (__half*)p
    SYMH(batchH, g_batchH);
    SYMH(wTH, g_wTH);
    SYMH(gTH, g_gTH);
    SYMH(tpH, g_tpH);         SYMH(tpL, g_tpL);
    SYMH(attnH, g_attnH);
    SYMH(featsTH, g_featsTH);
#undef SYMH

    static bool attr_done = false;
    if (!attr_done) {
        cudaFuncSetAttribute(gemm_hmma<1, 1, 1>,
                             cudaFuncAttributeMaxDynamicSharedMemorySize, SMEMB1);
        cudaFuncSetAttribute(gemm_hmma<1, 2, 0>,
                             cudaFuncAttributeMaxDynamicSharedMemorySize, SMEMB1);
        cudaFuncSetAttribute(gemm_hmma<3, 0, 0>,
                             cudaFuncAttributeMaxDynamicSharedMemorySize, SMEMB3);
        cudaFuncSetAttribute(out_gemm_areuse,
                             cudaFuncAttributeMaxDynamicSharedMemorySize, AR_SMEM);
        attr_done = true;
    }

    // converts
    cvt_kernel<<<32768, 256>>>(batch, batchH, (long)67108864);
    const dim3 tb(32, 8);
    transpose_cvt_kernel<<<dim3(AA / 32, FF / 32), tb>>>(a_w, wTH, FF, AA);
    transpose_cvt_kernel<<<dim3(AA / 32, FF / 32), tb>>>(
        b_w, wTH + 256 * 1024, FF, AA);
    transpose_cvt_kernel<<<dim3(FF / 32, FF / 32), tb>>>(g_w, gTH, FF, FF);

    // tp = batch @ [a_w|b_w] + bias : M=65536, N=512, K=1024 (1-pass, out hi/lo)
    gemm_hmma<1, 1, 1><<<dim3(4, 512, 1), 256, SMEMB1>>>(
        batchH, nullptr, wTH, nullptr, a_b, b_b, tpH, tpL, nullptr,
        512, 1024, 1024, 1024, 512, 1.0f, 0, 0, 0);

    // featsT[t][f][s]: per t, M=1024(f), N=256(s), K=1024 (1-pass, hi only)
    gemm_hmma<1, 2, 0><<<dim3(2, 8, 256), 256, SMEMB1>>>(
        gTH, nullptr, batchH, nullptr, g_b, nullptr, featsTH, nullptr, nullptr,
        256, 1024, 1024, 1024, 256, 1.0f, 0, (long)256 * 1024, (long)1024 * 256);

    // attn[t] = theta[t] @ phi[t]^T : per t M=N=256, K=256 (3-pass, hi only)
    gemm_hmma<3, 0, 0><<<dim3(2, 2, 256), 256, SMEMB3>>>(
        tpH, tpL, tpH + 256, tpL + 256, nullptr, nullptr, attnH, nullptr, nullptr,
        256, 256, 512, 512, 256, 1.0f, 131072, 131072, 65536);

    // out[t] = (attn[t] @ feats[t]) / 512 : A-reuse kernel
    out_gemm_areuse<<<dim3(2, 256), 256, AR_SMEM>>>(
        attnH, featsTH, out, 1.0f / (float)(SS + TT));
}

// round 11
// speedup vs baseline: 1.1278x; 1.1074x over previous
#include <cuda_runtime.h>
#include <cuda_fp16.h>
#include <cstdint>

// CrossInferenceBlock via fp16 mma.sync (HMMA), all stages 1-pass, occ-2 uniform:
//  tp    = batch @ [a_w|b_w] + bias   (65536 x 512)  hi only
//  featsT[t][f][s] = (batch @ g_w + g_b)^T per t     hi only
//  attn[t] = theta[t] @ phi[t]^T      (256 x 256)    hi only
//  out[t]  = (attn[t] @ feats[t])/512                fp32
// GEMM: C[m][n] = sum_k A[m,k]*B[n,k], all K-major fp16.

#define TT 256
#define SS 256
#define FF 1024
#define AA 256

// ------------------------------- static scratch
__device__ __align__(16) __half g_batchH[67108864];  // [65536][1024]
__device__ __align__(16) __half g_wTH[524288];       // [512][1024] = aT|bT (hi)
__device__ __align__(16) __half g_gTH[1048576];      // g_w^T (hi)
__device__ __align__(16) __half g_tpH[33554432];     // [65536][512] theta|phi
__device__ __align__(16) __half g_attnH[16777216];   // [65536][256]
__device__ __align__(16) __half g_featsTH[67108864]; // [256][1024][256]

// ------------------------------- helpers
__device__ __forceinline__ uint32_t smem_u32(const void* p) {
    uint32_t a;
    asm("{ .reg .u64 t; cvta.to.shared.u64 t, %1; cvt.u32.u64 %0, t; }"
        : "=r"(a) : "l"(p));
    return a;
}
__device__ __forceinline__ void cpasync16(uint32_t s, const void* g) {
    asm volatile("cp.async.cg.shared.global [%0], [%1], 16;" :: "r"(s), "l"(g));
}
__device__ __forceinline__ void cp_commit() { asm volatile("cp.async.commit_group;"); }
template <int N>
__device__ __forceinline__ void cp_wait() {
    asm volatile("cp.async.wait_group %0;" :: "n"(N));
}
__device__ __forceinline__ uint4 ldsm4(uint32_t a) {
    uint4 r;
    asm volatile("ldmatrix.sync.aligned.m8n8.x4.shared.b16 {%0,%1,%2,%3}, [%4];"
                 : "=r"(r.x), "=r"(r.y), "=r"(r.z), "=r"(r.w) : "r"(a));
    return r;
}
__device__ __forceinline__ void mma_f16(float* c, const uint4& a,
                                        uint32_t b0, uint32_t b1) {
    asm volatile(
        "mma.sync.aligned.m16n8k16.row.col.f32.f16.f16.f32 "
        "{%0,%1,%2,%3},{%4,%5,%6,%7},{%8,%9},{%0,%1,%2,%3};"
        : "+f"(c[0]), "+f"(c[1]), "+f"(c[2]), "+f"(c[3])
        : "r"(a.x), "r"(a.y), "r"(a.z), "r"(a.w), "r"(b0), "r"(b1));
}

// ------------------------------- converters
__global__ void cvt_kernel(const float* __restrict__ in, __half* __restrict__ oh,
                           long n) {
    long i = ((long)blockIdx.x * blockDim.x + threadIdx.x) * 8;
    if (i >= n) return;
    float4 v0 = *(const float4*)(in + i);
    float4 v1 = *(const float4*)(in + i + 4);
    __half2 a = __floats2half2_rn(v0.x, v0.y);
    __half2 b = __floats2half2_rn(v0.z, v0.w);
    __half2 c = __floats2half2_rn(v1.x, v1.y);
    __half2 d = __floats2half2_rn(v1.z, v1.w);
    *(uint4*)(oh + i) = make_uint4(*(uint32_t*)&a, *(uint32_t*)&b,
                                   *(uint32_t*)&c, *(uint32_t*)&d);
}

__global__ void transpose_cvt_kernel(const float* __restrict__ in,
                                     __half* __restrict__ oh, int R, int C) {
    __shared__ float t[32][33];
    int c0 = blockIdx.x * 32, r0 = blockIdx.y * 32;
    int x = threadIdx.x, y = threadIdx.y;  // 32 x 8
#pragma unroll
    for (int i = 0; i < 32; i += 8)
        t[y + i][x] = in[(long)(r0 + y + i) * C + c0 + x];
    __syncthreads();
#pragma unroll
    for (int i = 0; i < 32; i += 8)
        oh[(long)(c0 + y + i) * R + r0 + x] = __float2half_rn(t[x][y + i]);
}

// ------------------------------- GEMM: BM=128 BN=128 BK=64, 3-stage cp.async
static constexpr int TILE = 16384;  // 128 x 64 fp16
static constexpr int OFF_AH = 0;
static constexpr int OFF_BH = TILE;

// BMODE: 0 none, 1 col-bias (bias n<256 / bias2 n>=256), 2 row-bias (bias[m])
// OUTM : 0 = fp16, 2 = fp32
template <int BMODE, int OUTM>
__global__ void __launch_bounds__(256, 2) gemm_hmma(
    const __half* __restrict__ Ah, const __half* __restrict__ Bh,
    const float* __restrict__ bias, const float* __restrict__ bias2,
    __half* __restrict__ Ch, float* __restrict__ Cf,
    int N, int K, int lda, int ldb, int ldc, float scale,
    long sA, long sB, long sC)
{
    constexpr int STAGE = 2 * TILE;
    extern __shared__ __align__(1024) char smem[];
    const uint32_t sbase = smem_u32(smem);
    const int tid = threadIdx.x;
    const int wid = tid >> 5, lane = tid & 31;
    const long z = blockIdx.z;
    const int block_row = blockIdx.y * 128;
    const int block_col = blockIdx.x * 128;

    const __half* Az_h = Ah + z * sA + (long)block_row * lda;
    const __half* Bz_h = Bh + z * sB + (long)block_col * ldb;

    int c_row[4]; int c_co[4]; uint32_t c_so[4];
#pragma unroll
    for (int i = 0; i < 4; i++) {
        int q = tid + i * 256;
        int r = q >> 3, u = q & 7;
        c_row[i] = r;
        c_co[i] = u * 8;
        c_so[i] = (uint32_t)(r * 128 + ((u ^ (r & 7)) << 4));
    }

    auto load_stage = [&](int buf, int k0) {
        uint32_t sb = sbase + buf * STAGE;
#pragma unroll
        for (int i = 0; i < 4; i++) {
            long ga = (long)c_row[i] * lda + k0 + c_co[i];
            long gb = (long)c_row[i] * ldb + k0 + c_co[i];
            cpasync16(sb + OFF_AH + c_so[i], Az_h + ga);
            cpasync16(sb + OFF_BH + c_so[i], Bz_h + gb);
        }
    };

    const int wm = wid & 1, wn = wid >> 1;
    const int arow = wm * 64 + (lane & 15);
    const uint32_t asel = ((lane >> 4) & 1) * 16;
    const uint32_t axr = (uint32_t)((arow & 7) << 4);
    const int brow = wn * 32 + (lane & 7) + ((lane & 16) ? 8 : 0);
    const uint32_t bsel = (lane & 8) ? 16u : 0u;
    const uint32_t bxr = (uint32_t)((brow & 7) << 4);

    float acc[4][4][4];
#pragma unroll
    for (int a = 0; a < 4; a++)
#pragma unroll
        for (int b = 0; b < 4; b++)
#pragma unroll
            for (int c = 0; c < 4; c++) acc[a][b][c] = 0.0f;

    const int NT = K >> 6;
    load_stage(0, 0);
    cp_commit();
    if (NT > 1) load_stage(1, 64);
    cp_commit();

    int buf = 0;
    for (int it = 0; it < NT; it++) {
        cp_wait<1>();
        __syncthreads();
        if (it + 2 < NT) load_stage((it + 2) % 3, (it + 2) << 6);
        cp_commit();

        const uint32_t sb = sbase + buf * STAGE;
#pragma unroll
        for (int kk = 0; kk < 4; kk++) {
            uint4 ah[4], bhf[2];
#pragma unroll
            for (int mi = 0; mi < 4; mi++) {
                uint32_t ro = (uint32_t)((arow + mi * 16) * 128) +
                              (((uint32_t)(kk * 32) + asel) ^ axr);
                ah[mi] = ldsm4(sb + OFF_AH + ro);
            }
#pragma unroll
            for (int pi = 0; pi < 2; pi++) {
                uint32_t ro = (uint32_t)((brow + pi * 16) * 128) +
                              (((uint32_t)(kk * 32) + bsel) ^ bxr);
                bhf[pi] = ldsm4(sb + OFF_BH + ro);
            }
#pragma unroll
            for (int mi = 0; mi < 4; mi++) {
#pragma unroll
                for (int ni = 0; ni < 4; ni++) {
                    const int pi = ni >> 1;
                    const bool up = ni & 1;
                    uint32_t bh0 = up ? bhf[pi].z : bhf[pi].x;
                    uint32_t bh1 = up ? bhf[pi].w : bhf[pi].y;
                    mma_f16(acc[mi][ni], ah[mi], bh0, bh1);
                }
            }
        }
        buf = (buf + 1) % 3;
    }

    const int grow0 = block_row + wm * 64 + (lane >> 2);
    const int gcol0 = block_col + wn * 32 + (lane & 3) * 2;
#pragma unroll
    for (int mi = 0; mi < 4; mi++) {
#pragma unroll
        for (int ni = 0; ni < 4; ni++) {
            float v0 = acc[mi][ni][0], v1 = acc[mi][ni][1];
            float v2 = acc[mi][ni][2], v3 = acc[mi][ni][3];
            const int r0 = grow0 + mi * 16, r1 = r0 + 8;
            const int cc = gcol0 + ni * 8;
            if (BMODE == 1) {
                float b0 = (cc < 256) ? bias[cc] : bias2[cc - 256];
                float b1 = (cc + 1 < 256) ? bias[cc + 1] : bias2[cc + 1 - 256];
                v0 += b0; v1 += b1; v2 += b0; v3 += b1;
            }
            if (BMODE == 2) {
                float ba = bias[r0], bb = bias[r1];
                v0 += ba; v1 += ba; v2 += bb; v3 += bb;
            }
            v0 *= scale; v1 *= scale; v2 *= scale; v3 *= scale;
            const long o0 = z * sC + (long)r0 * ldc + cc;
            const long o1 = z * sC + (long)r1 * ldc + cc;
            if (OUTM == 0) {
                __half2 p0 = __floats2half2_rn(v0, v1);
                __half2 p1 = __floats2half2_rn(v2, v3);
                *(uint32_t*)(Ch + o0) = *(uint32_t*)&p0;
                *(uint32_t*)(Ch + o1) = *(uint32_t*)&p1;
            } else {
                *(float2*)(Cf + o0) = make_float2(v0, v1);
                *(float2*)(Cf + o1) = make_float2(v2, v3);
            }
        }
    }
}

static constexpr int SMEMB1 = 3 * 2 * TILE;  //  96 KB

// ------------------------------- launcher
extern "C" void kernel_launch(void* const* d_in, const int* in_sizes, int n_in,
                              void* d_out, int out_size)
{
    const float* batch = (const float*)d_in[0];
    const float* a_w   = (const float*)d_in[1];
    const float* a_b   = (const float*)d_in[2];
    const float* b_w   = (const float*)d_in[3];
    const float* b_b   = (const float*)d_in[4];
    const float* g_w   = (const float*)d_in[5];
    const float* g_b   = (const float*)d_in[6];
    float* out = (float*)d_out;

    void* p;
#define SYMH(v, s) cudaGetSymbolAddress(&p, s); __half* v = (__half*)p
    SYMH(batchH, g_batchH);
    SYMH(wTH, g_wTH);
    SYMH(gTH, g_gTH);
    SYMH(tpH, g_tpH);
    SYMH(attnH, g_attnH);
    SYMH(featsTH, g_featsTH);
#undef SYMH

    static bool attr_done = false;
    if (!attr_done) {
        cudaFuncSetAttribute(gemm_hmma<1, 0>,
                             cudaFuncAttributeMaxDynamicSharedMemorySize, SMEMB1);
        cudaFuncSetAttribute(gemm_hmma<2, 0>,
                             cudaFuncAttributeMaxDynamicSharedMemorySize, SMEMB1);
        cudaFuncSetAttribute(gemm_hmma<0, 0>,
                             cudaFuncAttributeMaxDynamicSharedMemorySize, SMEMB1);
        cudaFuncSetAttribute(gemm_hmma<0, 2>,
                             cudaFuncAttributeMaxDynamicSharedMemorySize, SMEMB1);
        attr_done = true;
    }

    // converts
    cvt_kernel<<<32768, 256>>>(batch, batchH, (long)67108864);
    const dim3 tb(32, 8);
    transpose_cvt_kernel<<<dim3(AA / 32, FF / 32), tb>>>(a_w, wTH, FF, AA);
    transpose_cvt_kernel<<<dim3(AA / 32, FF / 32), tb>>>(
        b_w, wTH + 256 * 1024, FF, AA);
    transpose_cvt_kernel<<<dim3(FF / 32, FF / 32), tb>>>(g_w, gTH, FF, FF);

    // tp = batch @ [a_w|b_w] + bias : M=65536, N=512, K=1024 (hi only)
    gemm_hmma<1, 0><<<dim3(4, 512, 1), 256, SMEMB1>>>(
        batchH, wTH, a_b, b_b, tpH, nullptr,
        512, 1024, 1024, 1024, 512, 1.0f, 0, 0, 0);

    // featsT[t][f][s]: per t, M=1024(f), N=256(s), K=1024 (hi only)
    gemm_hmma<2, 0><<<dim3(2, 8, 256), 256, SMEMB1>>>(
        gTH, batchH, g_b, nullptr, featsTH, nullptr,
        256, 1024, 1024, 1024, 256, 1.0f, 0, (long)256 * 1024, (long)1024 * 256);

    // attn[t] = theta[t] @ phi[t]^T : per t M=N=256, K=256 (1-pass, hi only)
    gemm_hmma<0, 0><<<dim3(2, 2, 256), 256, SMEMB1>>>(
        tpH, tpH + 256, nullptr, nullptr, attnH, nullptr,
        256, 256, 512, 512, 256, 1.0f, 131072, 131072, 65536);

    // out[t] = (attn[t] @ feats[t]) / 512 : per t M=256, N=1024, K=256 (fp32)
    gemm_hmma<0, 2><<<dim3(8, 2, 256), 256, SMEMB1>>>(
        attnH, featsTH, nullptr, nullptr, nullptr, out,
        1024, 256, 256, 256, 1024, 1.0f / (float)(SS + TT),
        65536, (long)1024 * 256, (long)256 * 1024);
}